// round 3
// baseline (speedup 1.0000x reference)
#include <cuda_runtime.h>

// AtmLayer fused kernel: per-thread column, all weights in shared memory.
// B = 131072 (from in_sizes[0]); outputs: t_direct(29,B), t_diffuse(29,B),
// e_direct(29,B,3), e_diffuse(29,B,3) concatenated flat in d_out (232*B f32).

#define TPB 256

// ---- compile-time scatter tables: per output row, contributing (gas net, comp idx) ----
// comp idx: 0=h2o 1=h2o_sq 2=o3 3=co2 4=n2o 5=ch4 6=u
__device__ constexpr int NETS[29][7] = {
    {23, 0,52,65,74,77,86},
    {24, 1,53,66,75,78,87},
    {25, 2,54,67,76,79,88},
    {26, 3,80,-1,-1,-1,-1},
    {27, 4,81,-1,-1,-1,-1},
    {28, 5,68,-1,-1,-1,-1},
    {29, 6,69,-1,-1,-1,-1},
    {30, 3,82,-1,-1,-1,-1},
    {31, 4,83,-1,-1,-1,-1},
    {32, 9,70,-1,-1,-1,-1},
    {33,10,71,-1,-1,-1,-1},
    {34,11,84,-1,-1,-1,-1},
    {35,12,85,-1,-1,-1,-1},
    {36,13,72,-1,-1,-1,-1},
    {37,14,73,-1,-1,-1,-1},
    {38,15,89,-1,-1,-1,-1},
    {39,16,90,-1,-1,-1,-1},
    {40,17,55,91,-1,-1,-1},
    {41,18,56,92,-1,-1,-1},
    {42,19,57,93,-1,-1,-1},
    {43,20,58,94,-1,-1,-1},
    {44,21,59,95,-1,-1,-1},
    {45,22,60,96,-1,-1,-1},
    {46,-1,-1,-1,-1,-1,-1},
    {47,-1,-1,-1,-1,-1,-1},
    {48,61,-1,-1,-1,-1,-1},
    {49,62,-1,-1,-1,-1,-1},
    {50,63,97,-1,-1,-1,-1},
    {51,64,98,-1,-1,-1,-1},
};
__device__ constexpr int CIDX[29][7] = {
    {1,0,2,3,4,5,6},
    {1,0,2,3,4,5,6},
    {1,0,2,3,4,5,6},
    {1,0,5,0,0,0,0},
    {1,0,5,0,0,0,0},
    {1,0,3,0,0,0,0},
    {1,0,3,0,0,0,0},
    {1,0,5,0,0,0,0},
    {1,0,5,0,0,0,0},
    {1,0,3,0,0,0,0},
    {1,0,3,0,0,0,0},
    {1,0,5,0,0,0,0},
    {1,0,5,0,0,0,0},
    {1,0,3,0,0,0,0},
    {1,0,3,0,0,0,0},
    {1,0,6,0,0,0,0},
    {1,0,6,0,0,0,0},
    {1,0,2,6,0,0,0},
    {1,0,2,6,0,0,0},
    {1,0,2,6,0,0,0},
    {1,0,2,6,0,0,0},
    {1,0,2,6,0,0,0},
    {1,0,2,6,0,0,0},
    {1,0,0,0,0,0,0},
    {1,0,0,0,0,0,0},
    {1,2,0,0,0,0,0},
    {1,2,0,0,0,0,0},
    {1,2,6,0,0,0,0},
    {1,2,6,0,0,0,0},
};

__device__ __forceinline__ float fast_elu(float x) {
    float e = __expf(x) - 1.0f;
    return x > 0.0f ? x : e;
}

// gas net g: input (x0,x1) -> hidden 8 (elu) -> relu(scalar)
__device__ __forceinline__ float gas_eval(int g, float x0, float x1,
                                          const float* sW1, const float* sB1,
                                          const float* sW2, const float* sB2)
{
    const float4* w1 = reinterpret_cast<const float4*>(sW1 + g * 16);
    float4 a0 = w1[0];  // W1[g][0][0..3]
    float4 a1 = w1[1];  // W1[g][0][4..7]
    float4 b0 = w1[2];  // W1[g][1][0..3]
    float4 b1 = w1[3];  // W1[g][1][4..7]
    const float4* bb = reinterpret_cast<const float4*>(sB1 + g * 8);
    float4 c0 = bb[0], c1 = bb[1];
    const float4* vv = reinterpret_cast<const float4*>(sW2 + g * 8);
    float4 v0 = vv[0], v1 = vv[1];
    float acc = sB2[g];
    float h;
    h = fast_elu(fmaf(x1, b0.x, fmaf(x0, a0.x, c0.x))); acc = fmaf(h, v0.x, acc);
    h = fast_elu(fmaf(x1, b0.y, fmaf(x0, a0.y, c0.y))); acc = fmaf(h, v0.y, acc);
    h = fast_elu(fmaf(x1, b0.z, fmaf(x0, a0.z, c0.z))); acc = fmaf(h, v0.z, acc);
    h = fast_elu(fmaf(x1, b0.w, fmaf(x0, a0.w, c0.w))); acc = fmaf(h, v0.w, acc);
    h = fast_elu(fmaf(x1, b1.x, fmaf(x0, a1.x, c1.x))); acc = fmaf(h, v1.x, acc);
    h = fast_elu(fmaf(x1, b1.y, fmaf(x0, a1.y, c1.y))); acc = fmaf(h, v1.y, acc);
    h = fast_elu(fmaf(x1, b1.z, fmaf(x0, a1.z, c1.z))); acc = fmaf(h, v1.z, acc);
    h = fast_elu(fmaf(x1, b1.w, fmaf(x0, a1.w, c1.w))); acc = fmaf(h, v1.w, acc);
    return fmaxf(acc, 0.0f);
}

__global__ void __launch_bounds__(TPB)
atm_layer_kernel(const float* __restrict__ temp,
                 const float* __restrict__ pressure,
                 const float* __restrict__ comp_h2o,
                 const float* __restrict__ comp_h2o_sq,
                 const float* __restrict__ comp_o3,
                 const float* __restrict__ comp_co2,
                 const float* __restrict__ comp_n2o,
                 const float* __restrict__ comp_ch4,
                 const float* __restrict__ comp_u,
                 const float* __restrict__ lwp,
                 const float* __restrict__ iwp,
                 const float* __restrict__ mu,
                 const float* __restrict__ mu_bar,
                 const float* __restrict__ gas_W1,   // (99,2,8)
                 const float* __restrict__ gas_b1,   // (99,8)
                 const float* __restrict__ gas_W2,   // (99,8,1)
                 const float* __restrict__ gas_b2,   // (99,1)
                 const float* __restrict__ lw_w,     // (29,1)
                 const float* __restrict__ iw_w,     // (29,1)
                 const float* __restrict__ ext_W1,   // (29,4,16)
                 const float* __restrict__ ext_b1,   // (29,16)
                 const float* __restrict__ ext_W2,   // (29,16,3)
                 const float* __restrict__ ext_b2,   // (29,3)
                 float* __restrict__ out,
                 int B)
{
    __shared__ __align__(16) float sW1[99 * 16];
    __shared__ __align__(16) float sB1[99 * 8];
    __shared__ __align__(16) float sW2[99 * 8];
    __shared__ __align__(16) float sB2[100];
    __shared__ __align__(16) float sEW1[29 * 64];   // [r][j(16)][i(4)] transposed
    __shared__ __align__(16) float sEB1[29 * 16];
    __shared__ __align__(16) float sEW2[29 * 64];   // [r][j(16)][k(4)] k=3 padded 0
    __shared__ __align__(16) float sEB2[88];
    __shared__ float sLW[29], sIW[29];

    const int tid = threadIdx.x;

    // ---- cooperative weight staging ----
    for (int i = tid; i < 99 * 16; i += TPB) sW1[i] = gas_W1[i];
    for (int i = tid; i < 99 * 8;  i += TPB) sB1[i] = gas_b1[i];
    for (int i = tid; i < 99 * 8;  i += TPB) sW2[i] = gas_W2[i];
    for (int i = tid; i < 99;      i += TPB) sB2[i] = gas_b2[i];
    for (int i = tid; i < 29 * 64; i += TPB) {
        int r = i >> 6, rem = i & 63, ii = rem >> 4, j = rem & 15;
        sEW1[(r << 6) + (j << 2) + ii] = ext_W1[i];       // transpose [i][j] -> [j][i]
    }
    for (int i = tid; i < 29 * 48; i += TPB) {
        int r = i / 48, rem = i % 48, j = rem / 3, k = rem % 3;
        sEW2[(r << 6) + (j << 2) + k] = ext_W2[i];        // pad stride 3 -> 4
    }
    for (int i = tid; i < 29 * 16; i += TPB) sEW2[(i << 2) + 3] = 0.0f;
    for (int i = tid; i < 29 * 16; i += TPB) sEB1[i] = ext_b1[i];
    for (int i = tid; i < 87;      i += TPB) sEB2[i] = ext_b2[i];
    for (int i = tid; i < 29;      i += TPB) { sLW[i] = lw_w[i]; sIW[i] = iw_w[i]; }
    __syncthreads();

    const int b = blockIdx.x * TPB + tid;
    if (b >= B) return;

    // ---- per-column scalar inputs ----
    const float x0 = temp[b];
    const float x1 = pressure[b];
    float c[7];
    c[0] = comp_h2o[b];
    c[1] = comp_h2o_sq[b];
    c[2] = comp_o3[b];
    c[3] = comp_co2[b];
    c[4] = comp_n2o[b];
    c[5] = comp_ch4[b];
    c[6] = comp_u[b];
    const float lwpv = lwp[b];
    const float iwpv = iwp[b];
    const float muv  = mu[b];
    const float mubv = mu_bar[b];
    const float rmu  = __fdividef(1.0f, muv);
    const float rmub = __fdividef(1.0f, mubv);

    const unsigned NB = (unsigned)B * 29u;
    float* __restrict__ out_tdir = out;
    float* __restrict__ out_tdif = out + NB;
    float* __restrict__ out_edir = out + 2u * NB;
    float* __restrict__ out_edif = out + 5u * NB;

    // ---- per-row streaming: gas gather -> ext nets (both passes fused) -> stores ----
    #pragma unroll
    for (int r = 0; r < 29; ++r) {
        float tau = 0.0f;
        #pragma unroll
        for (int t = 0; t < 7; ++t) {
            constexpr int dummy = 0; (void)dummy;
            const int g = NETS[r][t];
            if (g >= 0) {
                tau = fmaf(gas_eval(g, x0, x1, sW1, sB1, sW2, sB2), c[CIDX[r][t]], tau);
            }
        }
        const float tlw = sLW[r] * lwpv;
        const float tiw = sIW[r] * iwpv;
        const float tt  = tau + tlw + tiw;
        const float rtt = __fdividef(1.0f, tt);
        const float i1  = tlw * rtt;
        const float i2  = tiw * rtt;
        const float i3d = tt * rmu;
        const float i3f = tt * rmub;

        // ext net r, direct + diffuse passes share weight loads
        float ad0 = sEB2[r * 3 + 0], ad1 = sEB2[r * 3 + 1], ad2 = sEB2[r * 3 + 2];
        float af0 = ad0, af1 = ad1, af2 = ad2;
        const float4* w1 = reinterpret_cast<const float4*>(sEW1 + (r << 6));
        const float4* w2 = reinterpret_cast<const float4*>(sEW2 + (r << 6));
        const float*  bb = sEB1 + (r << 4);
        #pragma unroll
        for (int j = 0; j < 16; ++j) {
            const float4 w = w1[j];
            const float bj = bb[j];
            const float base = fmaf(i2, w.y, fmaf(i1, w.x, bj));
            const float zd = fmaf(muv,  w.w, fmaf(i3d, w.z, base));
            const float zf = fmaf(mubv, w.w, fmaf(i3f, w.z, base));
            const float hd = fast_elu(zd);
            const float hf = fast_elu(zf);
            const float4 v = w2[j];
            ad0 = fmaf(hd, v.x, ad0); ad1 = fmaf(hd, v.y, ad1); ad2 = fmaf(hd, v.z, ad2);
            af0 = fmaf(hf, v.x, af0); af1 = fmaf(hf, v.y, af1); af2 = fmaf(hf, v.z, af2);
        }
        ad0 = fmaxf(ad0, 0.0f); ad1 = fmaxf(ad1, 0.0f); ad2 = fmaxf(ad2, 0.0f);
        af0 = fmaxf(af0, 0.0f); af1 = fmaxf(af1, 0.0f); af2 = fmaxf(af2, 0.0f);

        // softmax (direct)
        {
            const float m = fmaxf(ad0, fmaxf(ad1, ad2));
            const float e0 = __expf(ad0 - m), e1 = __expf(ad1 - m), e2 = __expf(ad2 - m);
            const float inv = __fdividef(1.0f, e0 + e1 + e2);
            const unsigned base = ((unsigned)r * (unsigned)B + (unsigned)b) * 3u;
            out_edir[base + 0] = e0 * inv;
            out_edir[base + 1] = e1 * inv;
            out_edir[base + 2] = e2 * inv;
        }
        // softmax (diffuse)
        {
            const float m = fmaxf(af0, fmaxf(af1, af2));
            const float e0 = __expf(af0 - m), e1 = __expf(af1 - m), e2 = __expf(af2 - m);
            const float inv = __fdividef(1.0f, e0 + e1 + e2);
            const unsigned base = ((unsigned)r * (unsigned)B + (unsigned)b) * 3u;
            out_edif[base + 0] = e0 * inv;
            out_edif[base + 1] = e1 * inv;
            out_edif[base + 2] = e2 * inv;
        }
        out_tdir[(unsigned)r * (unsigned)B + (unsigned)b] = __expf(-i3d);
        out_tdif[(unsigned)r * (unsigned)B + (unsigned)b] = __expf(-i3f);
    }
}

extern "C" void kernel_launch(void* const* d_in, const int* in_sizes, int n_in,
                              void* d_out, int out_size)
{
    const int B = in_sizes[0];
    const int blocks = (B + TPB - 1) / TPB;
    atm_layer_kernel<<<blocks, TPB>>>(
        (const float*)d_in[0],  (const float*)d_in[1],  (const float*)d_in[2],
        (const float*)d_in[3],  (const float*)d_in[4],  (const float*)d_in[5],
        (const float*)d_in[6],  (const float*)d_in[7],  (const float*)d_in[8],
        (const float*)d_in[9],  (const float*)d_in[10], (const float*)d_in[11],
        (const float*)d_in[12], (const float*)d_in[13], (const float*)d_in[14],
        (const float*)d_in[15], (const float*)d_in[16], (const float*)d_in[17],
        (const float*)d_in[18], (const float*)d_in[19], (const float*)d_in[20],
        (const float*)d_in[21], (const float*)d_in[22],
        (float*)d_out, B);
}